// round 17
// baseline (speedup 1.0000x reference)
#include <cuda_runtime.h>
#include <cuda_bf16.h>
#include <cstdint>

// MaxUnpooling2D scatter-add.
//   updates/mask: [B=16, H=128, W=128, C=64]  -> 16,777,216 elements
//   output:       [B=16, OH=256, OW=256, C=64] -> 67,108,864 floats (268 MB)
// out_idx = (b<<22) | (mask & ~63) | c   (channel comes from the source element)
//
// R17: software-pipelined TWO-STREAM schedule with cross-stream events.
//   zero stream    : zero(0), zero(1), then zero(g) waits sDone[g-2]
//   scatter stream : scatter(g) waits zDone[g]
// Steady state: scatter(g) runs truly CONCURRENTLY with zero(g+1) (HW
// scheduler shares SMs dynamically -- no static role split), while the event
// chain caps the hot footprint at one scatter region + one zero region
// (33.5+33.5 MB < 126 MB L2). This removes R6's intra-kernel phase
// serialization (scatter waves THEN zero waves) without the L2 overflow that
// killed the uncoordinated two-stream variant (R16).
// Kernel bodies identical to the proven R6/R16 shapes (regs ~20).

static constexpr int B_DIM     = 16;
static constexpr int GROUP     = 2;
static constexpr int NGROUPS   = B_DIM / GROUP;         // 8
static constexpr int HWC       = 1 << 20;               // elems per batch
static constexpr int OUT_PER_B = 1 << 22;               // out floats per batch
static constexpr int THREADS   = 256;

static constexpr int SQ_PER_G  = GROUP * HWC / 4;       // 524,288 quads per group
static constexpr int S_BLOCKS  = SQ_PER_G / THREADS;    // 2048
static constexpr int ZV_PER_G  = GROUP * OUT_PER_B / 4; // 2,097,152 float4 per group
static constexpr int Z_BLOCKS  = ZV_PER_G / THREADS;    // 8192

// ---------------------------------------------------------------------------
__global__ void __launch_bounds__(THREADS)
zero_kernel(float4* __restrict__ out4)
{
    out4[blockIdx.x * THREADS + threadIdx.x] = make_float4(0.f, 0.f, 0.f, 0.f);
}

__global__ void __launch_bounds__(THREADS)
scatter_kernel(const float4* __restrict__ upd4,
               const int4*   __restrict__ msk4,
               float* __restrict__ out_g)
{
    int q  = blockIdx.x * THREADS + threadIdx.x;  // quad index in group
    int bl = q >> 18;                             // batch within group
    int c  = (q << 2) & 63;                       // channel of first lane

    float4 u = __ldg(&upd4[q]);
    int4   m = __ldg(&msk4[q]);

    int base = bl << 22;
    atomicAdd(&out_g[base | (m.x & ~63) | (c + 0)], u.x);
    atomicAdd(&out_g[base | (m.y & ~63) | (c + 1)], u.y);
    atomicAdd(&out_g[base | (m.z & ~63) | (c + 2)], u.z);
    atomicAdd(&out_g[base | (m.w & ~63) | (c + 3)], u.w);
}

// ---------------------------------------------------------------------------
extern "C" void kernel_launch(void* const* d_in, const int* in_sizes, int n_in,
                              void* d_out, int out_size)
{
    const float4* upd4 = (const float4*)d_in[0];
    const int4*   msk4 = (const int4*)d_in[1];
    float*        out  = (float*)d_out;

    // Host-side stream/event objects, created once (no device memory).
    static cudaStream_t sz = nullptr;                 // zero stream
    static cudaEvent_t  evFork = nullptr;
    static cudaEvent_t  zDone[NGROUPS];
    static cudaEvent_t  sDone[NGROUPS];
    if (sz == nullptr) {
        cudaStreamCreateWithFlags(&sz, cudaStreamNonBlocking);
        cudaEventCreateWithFlags(&evFork, cudaEventDisableTiming);
        for (int g = 0; g < NGROUPS; g++) {
            cudaEventCreateWithFlags(&zDone[g], cudaEventDisableTiming);
            cudaEventCreateWithFlags(&sDone[g], cudaEventDisableTiming);
        }
    }

    const size_t GRP_QUADS = (size_t)SQ_PER_G;
    const size_t GRP_OUT   = (size_t)GROUP * OUT_PER_B;
    cudaStream_t s0 = (cudaStream_t)0;                // scatter stream (capture)

    // Fork zero stream into the capture.
    cudaEventRecord(evFork, s0);
    cudaStreamWaitEvent(sz, evFork, 0);

    // Prime the pipeline: zero groups 0 and 1.
    zero_kernel<<<Z_BLOCKS, THREADS, 0, sz>>>((float4*)out);
    cudaEventRecord(zDone[0], sz);
    zero_kernel<<<Z_BLOCKS, THREADS, 0, sz>>>((float4*)(out + GRP_OUT));
    cudaEventRecord(zDone[1], sz);

    // Steady state: scatter(g) [stream s0]  ||  zero(g+2) [stream sz].
    for (int g = 0; g < NGROUPS; g++) {
        cudaStreamWaitEvent(s0, zDone[g], 0);
        scatter_kernel<<<S_BLOCKS, THREADS, 0, s0>>>(
            upd4 + (size_t)g * GRP_QUADS,
            msk4 + (size_t)g * GRP_QUADS,
            out  + (size_t)g * GRP_OUT);

        if (g + 2 < NGROUPS) {
            cudaEventRecord(sDone[g], s0);
            cudaStreamWaitEvent(sz, sDone[g], 0);     // bound L2 footprint
            zero_kernel<<<Z_BLOCKS, THREADS, 0, sz>>>(
                (float4*)(out + (size_t)(g + 2) * GRP_OUT));
            cudaEventRecord(zDone[g + 2], sz);
        }
    }
    // Join is implicit: the last stream-0 node waits zDone[NGROUPS-1], making
    // every zero-stream node an ancestor of the capture stream's tail.
}